// round 12
// baseline (speedup 1.0000x reference)
#include <cuda_runtime.h>
#include <cuda_fp16.h>
#include <cstdint>

// out[b,t,h] = (sum_c W[d[b],h,c]*f[b,t,c] + bias[d])*32 + pos[ts[b,t],h]
// B=32,T=1024,C=512,H=1024. fp16 mma.sync GEMM (fp32 accum), TMA bulk loads
// from pre-swizzled chunk-major scratch. Persistent CTAs; fragments batched
// two k-steps at a time (16 LDSM -> 64 HMMA) to cut dependency joints.

#define Bb 32
#define Tt 1024
#define Cc 512
#define Hh 1024
#define SCALE_F 32.0f

#define BM 128
#define BN 128
#define BK 64                 // fp16 k per chunk (128B rows)
#define NCH (Cc/BK)           // 8
#define STAGE_BYTES 32768     // A 16K + B 16K
#define NSTAGE 3
#define SM_MBAR (NSTAGE * STAGE_BYTES)      // 98304
#define SM_TOTAL (SM_MBAR + 64)

#define NTILES 2048           // 8(h) x 8(t) x 32(b)
#define GRID_P 296            // 148 SMs x 2 CTAs

#define HC4 131072            // H*C/4     (2^17)
#define NPAIR_F 2097152       // B*T*C/8   (2^21)

// Pre-swizzled chunk-major fp16 scratch: [b][chunk][row][128B]
__device__ __align__(128) __half g_fh[(size_t)Bb*Tt*Cc];
__device__ __align__(128) __half g_wh[(size_t)Bb*Hh*Cc];

__device__ __forceinline__ uint32_t s2u(const void* p) {
    uint32_t a;
    asm("{ .reg .u64 t; cvta.to.shared.u64 t, %1; cvt.u32.u64 %0, t; }" : "=r"(a) : "l"(p));
    return a;
}

__device__ __forceinline__ void ldmx4(uint32_t* r, uint32_t addr) {
    asm volatile("ldmatrix.sync.aligned.m8n8.x4.shared.b16 {%0,%1,%2,%3}, [%4];"
                 : "=r"(r[0]), "=r"(r[1]), "=r"(r[2]), "=r"(r[3]) : "r"(addr));
}

__device__ __forceinline__ void mma16816(float* d, const uint32_t* a, const uint32_t* b) {
    asm volatile(
        "mma.sync.aligned.m16n8k16.row.col.f32.f16.f16.f32 "
        "{%0,%1,%2,%3}, {%4,%5,%6,%7}, {%8,%9}, {%0,%1,%2,%3};"
        : "+f"(d[0]), "+f"(d[1]), "+f"(d[2]), "+f"(d[3])
        : "r"(a[0]), "r"(a[1]), "r"(a[2]), "r"(a[3]), "r"(b[0]), "r"(b[1]));
}

__device__ __forceinline__ uint32_t cvt2(float x, float y) {
    __half2 h = __floats2half2_rn(x, y);
    return *(uint32_t*)&h;
}

// Prep: fp32 -> fp16, gathered (W), chunk-major pre-swizzled.
// Each thread handles a PAIR of float4s (one 16B dst unit -> single uint4 store).
__global__ __launch_bounds__(256) void prep_all(const float4* __restrict__ f,
                                                const float4* __restrict__ W,
                                                const int* __restrict__ date_idx) {
    size_t idx = (size_t)blockIdx.x * 256 + threadIdx.x;   // 0 .. 2*NPAIR_F-1
    float4 v0, v1;
    char* base;
    int b, row, jg;
    if (idx < NPAIR_F) {
        b = (int)(idx >> 16);
        int rem = (int)(idx & 65535);
        row = rem >> 6; jg = rem & 63;
        v0 = f[2 * idx];
        v1 = f[2 * idx + 1];
        base = (char*)g_fh;
    } else {
        size_t k = idx - NPAIR_F;
        b = (int)(k >> 16);
        int rem = (int)(k & 65535);
        row = rem >> 6; jg = rem & 63;
        int d = date_idx[b];
        v0 = W[(size_t)d * HC4 + 2 * (size_t)rem];
        v1 = W[(size_t)d * HC4 + 2 * (size_t)rem + 1];
        base = (char*)g_wh;
    }
    uint4 o;
    o.x = cvt2(v0.x, v0.y);
    o.y = cvt2(v0.z, v0.w);
    o.z = cvt2(v1.x, v1.y);
    o.w = cvt2(v1.z, v1.w);
    int chunk = jg >> 3, jp = jg & 7;
    size_t off = ((((size_t)(b * 8 + chunk)) * 1024 + row) << 7)
               + ((uint32_t)(jp ^ (row & 7)) << 4);
    *(uint4*)(base + off) = o;
}

__device__ __forceinline__ void mbar_wait(uint32_t mb, uint32_t par) {
    uint32_t done;
    asm volatile("{\n .reg .pred p;\n mbarrier.try_wait.parity.acquire.cta.shared::cta.b64 p, [%1], %2;\n selp.b32 %0,1,0,p;\n}"
                 : "=r"(done) : "r"(mb), "r"(par) : "memory");
    if (!done) {
        asm volatile("{\n .reg .pred P1;\nWL_%=:\n mbarrier.try_wait.parity.acquire.cta.shared::cta.b64 P1, [%0], %1, 0x989680;\n @P1 bra.uni WD_%=;\n bra.uni WL_%=;\nWD_%=:\n}"
                     :: "r"(mb), "r"(par) : "memory");
    }
}

__global__ __launch_bounds__(128, 2) void gemm_main(const int* __restrict__ ts,
                                                    const int* __restrict__ date_idx,
                                                    const float* __restrict__ bias,
                                                    const float* __restrict__ pos,
                                                    float* __restrict__ out) {
    extern __shared__ char smem[];
    const uint32_t sb = s2u(smem);
    const int tid = threadIdx.x;
    const int bx = blockIdx.x;

    if (tid == 0) {
        #pragma unroll
        for (int s = 0; s < NSTAGE; s++)
            asm volatile("mbarrier.init.shared.b64 [%0], 1;"
                         :: "r"(sb + SM_MBAR + s * 8) : "memory");
    }
    __syncthreads();

    const int ntiles = (NTILES - 1 - bx) / GRID_P + 1;
    const int G = ntiles * NCH;            // flattened chunk count for this CTA

    // issue global chunk g: tile = bx + (g/8)*GRID_P, chunk = g&7
    auto issue = [&](int g) {
        const int tile = bx + (g >> 3) * GRID_P;
        const int chunk = g & 7;
        const int slot = g % NSTAGE;
        const int bb = tile >> 6;
        const int tt0 = ((tile >> 3) & 7) * BM;
        const int hh0 = (tile & 7) * BN;
        const uint32_t mb = sb + SM_MBAR + slot * 8;
        const uint32_t stb = sb + slot * STAGE_BYTES;
        const uint64_t srcA = (uint64_t)((const char*)g_fh
            + ((((size_t)bb * 8 + chunk) * 1024 + tt0) << 7));
        const uint64_t srcB = (uint64_t)((const char*)g_wh
            + ((((size_t)bb * 8 + chunk) * 1024 + hh0) << 7));
        asm volatile("mbarrier.arrive.expect_tx.shared.b64 _, [%0], %1;"
                     :: "r"(mb), "r"((uint32_t)STAGE_BYTES) : "memory");
        asm volatile("cp.async.bulk.shared::cluster.global.mbarrier::complete_tx::bytes "
                     "[%0], [%1], %2, [%3];"
                     :: "r"(stb), "l"(srcA), "r"(16384u), "r"(mb) : "memory");
        asm volatile("cp.async.bulk.shared::cluster.global.mbarrier::complete_tx::bytes "
                     "[%0], [%1], %2, [%3];"
                     :: "r"(stb + 16384u), "l"(srcB), "r"(16384u), "r"(mb) : "memory");
    };

    if (tid == 0) { issue(0); issue(1); issue(2); }

    const int w = tid >> 5, l = tid & 31;
    const int wm = w >> 1, wn = w & 1;                    // 2x2 warps
    const int m0 = wm * 64, n0 = wn * 64;                 // warp tile 64x64
    const int g4 = l >> 2, c4 = l & 3;

    const uint32_t swl = 4 * (l & 7);
    const uint32_t aRow = (uint32_t)(m0 + (l & 15)) * 128;
    const uint32_t aKsel = (l >> 4) * 4;
    const uint32_t bRow0 = (uint32_t)(n0 + ((l >> 4) * 8) + (l & 7)) * 128;
    const uint32_t bKsel = ((l >> 3) & 1) * 4;

    float acc[4][8][4] = {};

    #pragma unroll 1
    for (int g = 0; g < G; g++) {
        const int slot = g % NSTAGE;
        mbar_wait(sb + SM_MBAR + slot * 8, (uint32_t)((g / NSTAGE) & 1));
        const uint32_t stA = sb + slot * STAGE_BYTES;
        const uint32_t stB = stA + 16384;
        #pragma unroll
        for (int kp = 0; kp < 2; kp++) {
            // batch fragments for TWO k-steps: 16 LDSM, then 64 HMMA
            uint32_t a[2][4][4], bf[2][8][2];
            #pragma unroll
            for (int kh = 0; kh < 2; kh++) {
                const int ks = 2 * kp + kh;
                const uint32_t ak = (((uint32_t)(8 * ks) + aKsel) ^ swl) << 2;
                const uint32_t bk = (((uint32_t)(8 * ks) + bKsel) ^ swl) << 2;
                #pragma unroll
                for (int im = 0; im < 4; im++)
                    ldmx4(a[kh][im], stA + aRow + im * 2048 + ak);
                #pragma unroll
                for (int jp = 0; jp < 4; jp++) {
                    uint32_t r[4];
                    ldmx4(r, stB + bRow0 + jp * 2048 + bk);
                    bf[kh][2 * jp][0] = r[0]; bf[kh][2 * jp][1] = r[1];
                    bf[kh][2 * jp + 1][0] = r[2]; bf[kh][2 * jp + 1][1] = r[3];
                }
            }
            #pragma unroll
            for (int kh = 0; kh < 2; kh++)
                #pragma unroll
                for (int im = 0; im < 4; im++)
                    #pragma unroll
                    for (int jn = 0; jn < 8; jn++)
                        mma16816(acc[im][jn], a[kh][im], bf[kh][jn]);
        }
        __syncthreads();                         // all warps done reading slot
        if (tid == 0 && g + NSTAGE < G) issue(g + NSTAGE);

        if ((g & 7) == 7) {
            // epilogue for this tile (TMA for next tile's chunks already in flight)
            const int tile = bx + (g >> 3) * GRID_P;
            const int bb = tile >> 6;
            const int tt0 = ((tile >> 3) & 7) * BM;
            const int hh0 = (tile & 7) * BN;
            const int d = date_idx[bb];
            const float bv = bias[d];
            #pragma unroll
            for (int im = 0; im < 4; im++) {
                const int r0 = m0 + 16 * im + g4;
                const int tA = tt0 + r0, tB = tt0 + r0 + 8;
                const int pA = ts[bb * Tt + tA];
                const int pB = ts[bb * Tt + tB];
                const float* posA = pos + (size_t)pA * Hh;
                const float* posB = pos + (size_t)pB * Hh;
                float* outA = out + ((size_t)bb * Tt + tA) * Hh;
                float* outB = out + ((size_t)bb * Tt + tB) * Hh;
                #pragma unroll
                for (int jn = 0; jn < 8; jn++) {
                    const int col = hh0 + n0 + 8 * jn + 2 * c4;
                    float2 pv = *(const float2*)(posA + col);
                    float2 o;
                    o.x = (acc[im][jn][0] + bv) * SCALE_F + pv.x;
                    o.y = (acc[im][jn][1] + bv) * SCALE_F + pv.y;
                    *(float2*)(outA + col) = o;
                    pv = *(const float2*)(posB + col);
                    o.x = (acc[im][jn][2] + bv) * SCALE_F + pv.x;
                    o.y = (acc[im][jn][3] + bv) * SCALE_F + pv.y;
                    *(float2*)(outB + col) = o;
                }
            }
            #pragma unroll
            for (int im = 0; im < 4; im++)
                #pragma unroll
                for (int jn = 0; jn < 8; jn++)
                    #pragma unroll
                    for (int q = 0; q < 4; q++)
                        acc[im][jn][q] = 0.0f;
        }
    }
}

extern "C" void kernel_launch(void* const* d_in, const int* in_sizes, int n_in,
                              void* d_out, int out_size) {
    const float* features = (const float*)d_in[0];
    const int*   ts       = (const int*)d_in[1];
    const int*   date_idx = (const int*)d_in[2];
    const float* W        = (const float*)d_in[3];
    const float* bias     = (const float*)d_in[4];
    const float* pos      = (const float*)d_in[5];
    float* out = (float*)d_out;

    cudaFuncSetAttribute(gemm_main, cudaFuncAttributeMaxDynamicSharedMemorySize, SM_TOTAL);

    prep_all<<<(2 * NPAIR_F) / 256, 256>>>((const float4*)features, (const float4*)W, date_idx);
    gemm_main<<<GRID_P, 128, SM_TOTAL>>>(ts, date_idx, bias, pos, out);
}